// round 12
// baseline (speedup 1.0000x reference)
#include <cuda_runtime.h>
#include <cuda_fp16.h>
#include <cstdint>

#define B_    256
#define NI    64
#define L_    128
#define H_    128
#define K_    40
#define MTOT  (B_ * K_)          /* 10240 rows */
#define GATES 384

typedef unsigned long long ull;

// ---------------------------------------------------------------------------
// Device scratch (fp16 activations/weights; fp32 hold state)
// ---------------------------------------------------------------------------
__device__ __align__(256) __half g_x16[MTOT * H_];
__device__ __align__(256) __half g_h16[MTOT * H_];
__device__ __align__(256) float  g_h32[MTOT * H_];
__device__ __align__(256) __half g_h216[MTOT * H_];
__device__ __align__(256) float  g_h232[MTOT * H_];
__device__ __align__(256) __half g_wih_hi[GATES * H_];
__device__ __align__(256) __half g_wih_lo[GATES * H_];
__device__ __align__(256) __half g_whh_hi[GATES * H_];
__device__ __align__(256) __half g_whh_lo[GATES * H_];

// ---------------------------------------------------------------------------
// Helpers
// ---------------------------------------------------------------------------
__device__ __forceinline__ uint32_t smem_u32(const void* p) {
    uint32_t a;
    asm("{ .reg .u64 t; cvta.to.shared.u64 t, %1; cvt.u32.u64 %0, t; }"
        : "=r"(a) : "l"(p));
    return a;
}
__device__ __forceinline__ void cp16(uint32_t dst, const void* src) {
    asm volatile("cp.async.cg.shared.global [%0], [%1], 16;"
                 :: "r"(dst), "l"(src) : "memory");
}
#define CP_COMMIT() asm volatile("cp.async.commit_group;" ::: "memory")
#define CP_WAIT0()  asm volatile("cp.async.wait_group 0;" ::: "memory")
#define NB(id)      asm volatile("bar.sync %0, 128;" :: "r"((id) + 1) : "memory")

__device__ __forceinline__ void ldm4(uint32_t* a, uint32_t addr) {
    asm volatile("ldmatrix.sync.aligned.m8n8.x4.shared.b16 {%0,%1,%2,%3}, [%4];"
                 : "=r"(a[0]), "=r"(a[1]), "=r"(a[2]), "=r"(a[3]) : "r"(addr));
}
__device__ __forceinline__ float2 lds2f(uint32_t addr) {
    float2 v;
    asm volatile("ld.shared.v2.f32 {%0,%1}, [%2];"
                 : "=f"(v.x), "=f"(v.y) : "r"(addr));
    return v;
}
__device__ __forceinline__ void hmma(float* c, const uint32_t* a,
                                     uint32_t b0, uint32_t b1) {
    asm volatile("mma.sync.aligned.m16n8k16.row.col.f32.f16.f16.f32 "
                 "{%0,%1,%2,%3}, {%4,%5,%6,%7}, {%8,%9}, {%0,%1,%2,%3};"
                 : "+f"(c[0]), "+f"(c[1]), "+f"(c[2]), "+f"(c[3])
                 : "r"(a[0]), "r"(a[1]), "r"(a[2]), "r"(a[3]),
                   "r"(b0), "r"(b1));
}

__device__ __forceinline__ ull pk2(float v) {
    ull r; asm("mov.b64 %0, {%1, %1};" : "=l"(r) : "f"(v)); return r;
}
__device__ __forceinline__ float2 upk(ull v) {
    float2 f; asm("mov.b64 {%0, %1}, %2;" : "=f"(f.x), "=f"(f.y) : "l"(v)); return f;
}
__device__ __forceinline__ void fma2(ull& d, ull a, ull b) {
    asm("fma.rn.f32x2 %0, %1, %2, %0;" : "+l"(d) : "l"(a), "l"(b));
}
__device__ __forceinline__ ull ld2(const float* p) { return *(const ull*)p; }

__device__ __forceinline__ float sigm(float x) {
    return __fdividef(1.0f, 1.0f + __expf(-x));
}
__device__ __forceinline__ float tanh_(float x) {
    return __fdividef(2.0f, 1.0f + __expf(-2.0f * x)) - 1.0f;
}
// pack two floats into f16x2 (lo = a, hi = b)
__device__ __forceinline__ uint32_t f16x2_of(float a, float b) {
    uint32_t r;
    asm("cvt.rn.f16x2.f32 %0, %1, %2;" : "=r"(r) : "f"(b), "f"(a));
    return r;
}

// ---------------------------------------------------------------------------
// K1: split weights into fp16 hi/lo
// ---------------------------------------------------------------------------
__global__ void prep_kernel(const float* __restrict__ w_ih,
                            const float* __restrict__ w_hh) {
    int idx = blockIdx.x * blockDim.x + threadIdx.x;
    if (idx < GATES * H_) {
        float wi = w_ih[idx];
        __half hi = __float2half(wi);
        g_wih_hi[idx] = hi;
        g_wih_lo[idx] = __float2half(wi - __half2float(hi));
        float wh = w_hh[idx];
        __half hh = __float2half(wh);
        g_whh_hi[idx] = hh;
        g_whh_lo[idx] = __float2half(wh - __half2float(hh));
    }
}

// ---------------------------------------------------------------------------
// K2: gather + adj GEMM -> x (a) fp16, h (ev) fp16 + fp32 hold.
// ---------------------------------------------------------------------------
__global__ __launch_bounds__(256, 1)
void gather_adj_kernel(const float* __restrict__ seq_out,
                       const int*   __restrict__ target_idxs,
                       const int*   __restrict__ nid2rows,
                       const int*   __restrict__ ev_nids,
                       const float* __restrict__ adj,
                       const float* __restrict__ adj_bias) {
    __shared__ float s_h[K_ * H_];
    __shared__ float s_adj[K_ * K_];

    const int b    = blockIdx.x;
    const int tid  = threadIdx.x;
    const int warp = tid >> 5;
    const int lane = tid & 31;
    const int r0   = warp * 5;
    const int c0   = lane * 2;
    const int c1   = lane * 2 + 64;

    for (int i = tid; i < K_ * K_; i += 256)
        s_adj[i] = adj[b * K_ * K_ + i];

    #pragma unroll
    for (int rr = 0; rr < 5; rr++) {
        int k   = r0 + rr;
        int nid = ev_nids[b * K_ + k];
        int row = nid2rows[b * NI + nid];
        long long gi = (long long)b * NI + row;
        int t = target_idxs[gi];
        const float4* src = reinterpret_cast<const float4*>(
            seq_out + (gi * L_ + t) * (long long)H_);
        reinterpret_cast<float4*>(s_h + k * H_)[lane] = src[lane];
    }
    __syncthreads();

    ull bias0 = ld2(adj_bias + c0);
    ull bias1 = ld2(adj_bias + c1);
    ull acc[5][2];
    #pragma unroll
    for (int r = 0; r < 5; r++) { acc[r][0] = bias0; acc[r][1] = bias1; }

    for (int i = 0; i < K_; i++) {
        ull e0 = ld2(s_h + i * H_ + c0);
        ull e1 = ld2(s_h + i * H_ + c1);
        #pragma unroll
        for (int r = 0; r < 5; r++) {
            ull av = pk2(s_adj[i * K_ + r0 + r]);
            fma2(acc[r][0], av, e0);
            fma2(acc[r][1], av, e1);
        }
    }

    #pragma unroll
    for (int r = 0; r < 5; r++) {
        int gr = b * K_ + r0 + r;
        float2 a0 = upk(acc[r][0]);
        float2 a1 = upk(acc[r][1]);
        *(uint32_t*)(g_x16 + gr * H_ + c0) = f16x2_of(a0.x, a0.y);
        *(uint32_t*)(g_x16 + gr * H_ + c1) = f16x2_of(a1.x, a1.y);

        float2 e0 = upk(ld2(s_h + (r0 + r) * H_ + c0));
        float2 e1 = upk(ld2(s_h + (r0 + r) * H_ + c1));
        *(float2*)(g_h32 + gr * H_ + c0) = e0;
        *(float2*)(g_h32 + gr * H_ + c1) = e1;
        *(uint32_t*)(g_h16 + gr * H_ + c0) = f16x2_of(e0.x, e0.y);
        *(uint32_t*)(g_h16 + gr * H_ + c1) = f16x2_of(e1.x, e1.y);
    }
}

// ---------------------------------------------------------------------------
// K3: one GRU pass via fp16 HMMA, 2-term split, 16 warps (4/SMSP).
// Grid (32, 4): CTA = 64 rows x 32 h-cols, 5 M-tiles, 512 threads.
// 16 warps = 4 row-groups (16 rows) x 4 col-groups (8 h-cols).
// Warp computes all 6 gate blocks for its rows x cols -> register combine.
// W smem layout interleaves hi/lo rows per gate block so ONE ldmatrix.x4
// fetches both emulation terms' B fragments (m0,m1=hi; m2,m3=lo).
// ---------------------------------------------------------------------------
#define PITCH    272                      /* bytes per A/W smem row */
#define A_TSZ    (64 * PITCH)             /* 17408 */
#define SW_OFF   (2 * A_TSZ)              /* 34816 */
#define W_TOTSZ  (384 * PITCH)            /* 104448 */
#define HOLD_OFF (SW_OFF + W_TOTSZ)       /* 139264 */
#define HPITCHB  144                      /* 36 floats, 16B aligned rows */
#define HOLD_SZ  (64 * HPITCHB)           /* 9216 */
#define SMEM_TOT (HOLD_OFF + 2 * HOLD_SZ) /* 157696 */
#define NTILES   5

__global__ __launch_bounds__(512, 1)
void gru_pass_kernel(const __half* __restrict__ x16,
                     const __half* __restrict__ h16,
                     const float* __restrict__ hold,
                     const __half* __restrict__ wih_hi,
                     const __half* __restrict__ wih_lo,
                     const __half* __restrict__ whh_hi,
                     const __half* __restrict__ whh_lo,
                     const float* __restrict__ b_ih,
                     const float* __restrict__ b_hh,
                     float* __restrict__ out32,
                     __half* __restrict__ out16) {
    extern __shared__ __align__(16) char smem[];
    const uint32_t sb  = smem_u32(smem);
    const int tid   = threadIdx.x;
    const int wid   = tid >> 5;
    const int lane  = tid & 31;
    const int ycol0 = blockIdx.y * 32;
    const int m0    = blockIdx.x * NTILES;      // first M-tile

    const int cgrp  = wid >> 2;            // 0..3 col group (8 h-cols)
    const int rowg  = wid & 3;             // 0..3 row group (16 rows)
    const int mrows = rowg * 16;
    const int gt    = cgrp * 32 + lane;    // row-group-local tid 0..127

    // ---- per-row-group prefetch: A slices (x16, h16) + hold -----------------
    const __half* asrc[2] = {x16, h16};
    auto loadA = [&](int m, int pb) {
        #pragma unroll
        for (int t2 = 0; t2 < 2; t2++) {
            const __half* src = asrc[t2] + ((size_t)m * 64 + mrows) * H_;
            uint32_t dst = sb + t2 * A_TSZ + mrows * PITCH;
            #pragma unroll
            for (int c = gt; c < 256; c += 128) {       // 16 rows x 16 chunks
                int row = c >> 4, cw = c & 15;
                cp16(dst + row * PITCH + cw * 16, src + row * H_ + cw * 8);
            }
        }
        // hold slice: 16 rows x 32 cols f32 (8 chunks/row) = 128 chunks
        {
            const float* src = hold + ((size_t)m * 64 + mrows) * H_ + ycol0;
            uint32_t dst = sb + HOLD_OFF + pb * HOLD_SZ + mrows * HPITCHB;
            int row = gt >> 3, cw = gt & 7;
            cp16(dst + row * HPITCHB + cw * 16, src + row * H_ + cw * 4);
        }
    };

    // ---- W load (once): 384 rows = 24 blocks of 16 (8 hi rows + 8 lo rows) --
    // block id = (side*3 + gate)*4 + colgroup; source gate-matrix row =
    // gate*128 + ycol0 + colgroup*8 + r8, from {w_hi | w_lo} of that side.
    {
        const __half* wsrc[4] = {wih_hi, wih_lo, whh_hi, whh_lo};
        #pragma unroll
        for (int c = tid; c < 6144; c += 512) {         // 384 rows x 16 chunks
            int gp = c >> 4, cw = c & 15;
            int blkid = gp >> 4;                        // 0..23
            int side  = blkid / 12;
            int gate  = (blkid % 12) >> 2;
            int cgr   = blkid & 3;
            int hl    = (gp >> 3) & 1;
            int r8    = gp & 7;
            const __half* src = wsrc[side * 2 + hl]
                + (size_t)(gate * H_ + ycol0 + cgr * 8 + r8) * H_ + cw * 8;
            cp16(sb + SW_OFF + gp * PITCH + cw * 16, src);
        }
    }
    loadA(m0, 0);
    CP_COMMIT();
    CP_WAIT0();
    __syncthreads();                       // W + first A/hold visible

    // ---- fragment address constants -----------------------------------------
    // A ldmatrix.x4 (m16): lanes 0-15 rows 0-15 (k lo), 16-31 same rows (+16B)
    const uint32_t a_lanoff = (uint32_t)(lane & 15) * PITCH
                            + ((lane >> 4) & 1) * 16;
    // W ldmatrix.x4: m0 = hi k-lo, m1 = hi k-hi, m2 = lo k-lo, m3 = lo k-hi
    const uint32_t b_lanoff =
        (uint32_t)((lane & 7) + ((lane >> 4) << 3)) * PITCH
        + (((lane >> 3) & 1) * 16);

    // W row offset per gate block (0..2: ih r/z/n, 3..5: hh r/z/n)
    uint32_t wrow_off[6];
    #pragma unroll
    for (int blk = 0; blk < 6; blk++)
        wrow_off[blk] = (uint32_t)((blk * 4 + cgrp) * 16) * PITCH + b_lanoff;

    // ---- epilogue constants (biases hoisted) ---------------------------------
    const int e_colp = ycol0 + cgrp * 8 + (lane & 3) * 2;   // even col pair
    const float2 BIr = *(const float2*)(b_ih + e_colp);
    const float2 BIz = *(const float2*)(b_ih + 128 + e_colp);
    const float2 BIn = *(const float2*)(b_ih + 256 + e_colp);
    const float2 BHr = *(const float2*)(b_hh + e_colp);
    const float2 BHz = *(const float2*)(b_hh + 128 + e_colp);
    const float2 BHn = *(const float2*)(b_hh + 256 + e_colp);
    const uint32_t h_lanoff = (uint32_t)(cgrp * 8 + (lane & 3) * 2) * 4;

    int pb = 0;
    #pragma unroll 1
    for (int it = 0; it < NTILES; it++) {
        const int m     = m0 + it;
        const int mrow0 = m * 64;

        // ---- MMA compute: all 6 gate blocks, 2-term fp16 split ----------------
        float acc[6][4];
        #pragma unroll
        for (int j = 0; j < 6; j++)
            #pragma unroll
            for (int q = 0; q < 4; q++) acc[j][q] = 0.0f;

        const uint32_t Ax = sb + 0 * A_TSZ + mrows * PITCH + a_lanoff; // x16
        const uint32_t Ah = sb + 1 * A_TSZ + mrows * PITCH + a_lanoff; // h16
        const uint32_t Wb = sb + SW_OFF;

        #pragma unroll
        for (int ks = 0; ks < 8; ks++) {
            uint32_t xf[4], hf[4];
            ldm4(xf, Ax + ks * 32);
            ldm4(hf, Ah + ks * 32);
            #pragma unroll
            for (int blk = 0; blk < 6; blk++) {
                const uint32_t* a = (blk < 3) ? xf : hf;
                uint32_t w[4];
                ldm4(w, Wb + wrow_off[blk] + ks * 32);
                hmma(acc[blk], a, w[0], w[1]);      // term 1: a * w_hi
                hmma(acc[blk], a, w[2], w[3]);      // term 2: a * w_lo
            }
        }
        NB(rowg);                          // row-group's A slice fully consumed

        // ---- prefetch next A + hold (overlaps epilogue) -----------------------
        if (it + 1 < NTILES) { loadA(m + 1, pb ^ 1); CP_COMMIT(); }

        // ---- register epilogue: combine gates -> h' ---------------------------
        const uint32_t hbase = sb + HOLD_OFF + pb * HOLD_SZ + h_lanoff;
        #pragma unroll
        for (int half = 0; half < 2; half++) {
            int row = mrows + (lane >> 2) + half * 8;
            int q0  = half * 2;
            float2 ho = lds2f(hbase + row * HPITCHB);
            float r0 = sigm(acc[0][q0]     + BIr.x + acc[3][q0]     + BHr.x);
            float r1 = sigm(acc[0][q0 + 1] + BIr.y + acc[3][q0 + 1] + BHr.y);
            float z0 = sigm(acc[1][q0]     + BIz.x + acc[4][q0]     + BHz.x);
            float z1 = sigm(acc[1][q0 + 1] + BIz.y + acc[4][q0 + 1] + BHz.y);
            float n0 = tanh_(acc[2][q0]     + BIn.x + r0 * (acc[5][q0]     + BHn.x));
            float n1 = tanh_(acc[2][q0 + 1] + BIn.y + r1 * (acc[5][q0 + 1] + BHn.y));
            float hn0 = (1.0f - z0) * n0 + z0 * ho.x;
            float hn1 = (1.0f - z1) * n1 + z1 * ho.y;
            long long idx = (long long)(mrow0 + row) * H_ + e_colp;
            *(float2*)(out32 + idx) = make_float2(hn0, hn1);
            if (out16)
                *(uint32_t*)(out16 + idx) = f16x2_of(hn0, hn1);
        }

        if (it + 1 < NTILES) { CP_WAIT0(); }
        NB(rowg);                          // next A/hold ready for row group
        pb ^= 1;
    }
}

// ---------------------------------------------------------------------------
extern "C" void kernel_launch(void* const* d_in, const int* in_sizes, int n_in,
                              void* d_out, int out_size) {
    const float* seq_out     = (const float*)d_in[0];
    const int*   target_idxs = (const int*)  d_in[1];
    const int*   nid2rows    = (const int*)  d_in[2];
    const int*   ev_nids     = (const int*)  d_in[3];
    const float* adj         = (const float*)d_in[4];
    const float* adj_bias    = (const float*)d_in[5];
    const float* w_ih        = (const float*)d_in[6];
    const float* w_hh        = (const float*)d_in[7];
    const float* b_ih        = (const float*)d_in[8];
    const float* b_hh        = (const float*)d_in[9];
    float* out = (float*)d_out;

    static bool attr_set = false;
    if (!attr_set) {
        cudaFuncSetAttribute(gru_pass_kernel,
                             cudaFuncAttributeMaxDynamicSharedMemorySize,
                             SMEM_TOT);
        attr_set = true;
    }

    prep_kernel<<<(GATES * H_ + 255) / 256, 256>>>(w_ih, w_hh);
    gather_adj_kernel<<<B_, 256>>>(seq_out, target_idxs, nid2rows, ev_nids,
                                   adj, adj_bias);

    __half *x16_p, *h16_p, *h216_p;
    __half *wihh_p, *wihl_p, *whhh_p, *whhl_p;
    float *h32_p, *h232_p;
    cudaGetSymbolAddress((void**)&x16_p,  g_x16);
    cudaGetSymbolAddress((void**)&h16_p,  g_h16);
    cudaGetSymbolAddress((void**)&h216_p, g_h216);
    cudaGetSymbolAddress((void**)&h32_p,  g_h32);
    cudaGetSymbolAddress((void**)&h232_p, g_h232);
    cudaGetSymbolAddress((void**)&wihh_p, g_wih_hi);
    cudaGetSymbolAddress((void**)&wihl_p, g_wih_lo);
    cudaGetSymbolAddress((void**)&whhh_p, g_whh_hi);
    cudaGetSymbolAddress((void**)&whhl_p, g_whh_lo);

    dim3 grid(MTOT / (64 * NTILES), 4);    // (32, 4) = 128 CTAs, 1 wave
    // pass 1: x = a, h = ev  -> h1 (fp32 + fp16 into fresh buffers)
    gru_pass_kernel<<<grid, 512, SMEM_TOT>>>(
        x16_p, h16_p, h32_p,
        wihh_p, wihl_p, whhh_p, whhl_p, b_ih, b_hh,
        h232_p, h216_p);
    // pass 2: x = h = h1 -> d_out
    gru_pass_kernel<<<grid, 512, SMEM_TOT>>>(
        h216_p, h216_p, h232_p,
        wihh_p, wihl_p, whhh_p, whhl_p, b_ih, b_hh,
        out, nullptr);
}

// round 13
// speedup vs baseline: 1.4312x; 1.4312x over previous
#include <cuda_runtime.h>
#include <cuda_fp16.h>
#include <cstdint>

#define B_    256
#define NI    64
#define L_    128
#define H_    128
#define K_    40
#define MTOT  (B_ * K_)          /* 10240 rows */
#define GATES 384

typedef unsigned long long ull;

// ---------------------------------------------------------------------------
// Device scratch (fp16 activations/weights; fp32 hold state)
// ---------------------------------------------------------------------------
__device__ __align__(256) __half g_x16[MTOT * H_];
__device__ __align__(256) __half g_h16[MTOT * H_];
__device__ __align__(256) float  g_h32[MTOT * H_];
__device__ __align__(256) __half g_h216[MTOT * H_];
__device__ __align__(256) float  g_h232[MTOT * H_];
__device__ __align__(256) __half g_wih16[GATES * H_];
__device__ __align__(256) __half g_whh16[GATES * H_];

// ---------------------------------------------------------------------------
// Helpers
// ---------------------------------------------------------------------------
__device__ __forceinline__ uint32_t smem_u32(const void* p) {
    uint32_t a;
    asm("{ .reg .u64 t; cvta.to.shared.u64 t, %1; cvt.u32.u64 %0, t; }"
        : "=r"(a) : "l"(p));
    return a;
}
__device__ __forceinline__ void cp16(uint32_t dst, const void* src) {
    asm volatile("cp.async.cg.shared.global [%0], [%1], 16;"
                 :: "r"(dst), "l"(src) : "memory");
}
#define CP_COMMIT() asm volatile("cp.async.commit_group;" ::: "memory")
#define CP_WAIT0()  asm volatile("cp.async.wait_group 0;" ::: "memory")
#define NB(id)      asm volatile("bar.sync %0, 128;" :: "r"((id) + 1) : "memory")

__device__ __forceinline__ void ldm4(uint32_t* a, uint32_t addr) {
    asm volatile("ldmatrix.sync.aligned.m8n8.x4.shared.b16 {%0,%1,%2,%3}, [%4];"
                 : "=r"(a[0]), "=r"(a[1]), "=r"(a[2]), "=r"(a[3]) : "r"(addr));
}
__device__ __forceinline__ void ldm2(uint32_t* a, uint32_t addr) {
    asm volatile("ldmatrix.sync.aligned.m8n8.x2.shared.b16 {%0,%1}, [%2];"
                 : "=r"(a[0]), "=r"(a[1]) : "r"(addr));
}
__device__ __forceinline__ float2 lds2f(uint32_t addr) {
    float2 v;
    asm volatile("ld.shared.v2.f32 {%0,%1}, [%2];"
                 : "=f"(v.x), "=f"(v.y) : "r"(addr));
    return v;
}
__device__ __forceinline__ void hmma(float* c, const uint32_t* a,
                                     uint32_t b0, uint32_t b1) {
    asm volatile("mma.sync.aligned.m16n8k16.row.col.f32.f16.f16.f32 "
                 "{%0,%1,%2,%3}, {%4,%5,%6,%7}, {%8,%9}, {%0,%1,%2,%3};"
                 : "+f"(c[0]), "+f"(c[1]), "+f"(c[2]), "+f"(c[3])
                 : "r"(a[0]), "r"(a[1]), "r"(a[2]), "r"(a[3]),
                   "r"(b0), "r"(b1));
}

__device__ __forceinline__ ull pk2(float v) {
    ull r; asm("mov.b64 %0, {%1, %1};" : "=l"(r) : "f"(v)); return r;
}
__device__ __forceinline__ float2 upk(ull v) {
    float2 f; asm("mov.b64 {%0, %1}, %2;" : "=f"(f.x), "=f"(f.y) : "l"(v)); return f;
}
__device__ __forceinline__ void fma2(ull& d, ull a, ull b) {
    asm("fma.rn.f32x2 %0, %1, %2, %0;" : "+l"(d) : "l"(a), "l"(b));
}
__device__ __forceinline__ ull ld2(const float* p) { return *(const ull*)p; }

__device__ __forceinline__ float sigm(float x) {
    return __fdividef(1.0f, 1.0f + __expf(-x));
}
__device__ __forceinline__ float tanh_(float x) {
    return __fdividef(2.0f, 1.0f + __expf(-2.0f * x)) - 1.0f;
}
// pack two floats into f16x2 (lo = a, hi = b)
__device__ __forceinline__ uint32_t f16x2_of(float a, float b) {
    uint32_t r;
    asm("cvt.rn.f16x2.f32 %0, %1, %2;" : "=r"(r) : "f"(b), "f"(a));
    return r;
}

// ---------------------------------------------------------------------------
// K1: convert weights to fp16
// ---------------------------------------------------------------------------
__global__ void prep_kernel(const float* __restrict__ w_ih,
                            const float* __restrict__ w_hh) {
    int idx = blockIdx.x * blockDim.x + threadIdx.x;
    if (idx < GATES * H_) {
        g_wih16[idx] = __float2half(w_ih[idx]);
        g_whh16[idx] = __float2half(w_hh[idx]);
    }
}

// ---------------------------------------------------------------------------
// K2: gather + adj GEMM -> x (a) fp16, h (ev) fp16 + fp32 hold.
// ---------------------------------------------------------------------------
__global__ __launch_bounds__(256, 1)
void gather_adj_kernel(const float* __restrict__ seq_out,
                       const int*   __restrict__ target_idxs,
                       const int*   __restrict__ nid2rows,
                       const int*   __restrict__ ev_nids,
                       const float* __restrict__ adj,
                       const float* __restrict__ adj_bias) {
    __shared__ float s_h[K_ * H_];
    __shared__ float s_adj[K_ * K_];

    const int b    = blockIdx.x;
    const int tid  = threadIdx.x;
    const int warp = tid >> 5;
    const int lane = tid & 31;
    const int r0   = warp * 5;
    const int c0   = lane * 2;
    const int c1   = lane * 2 + 64;

    for (int i = tid; i < K_ * K_; i += 256)
        s_adj[i] = adj[b * K_ * K_ + i];

    #pragma unroll
    for (int rr = 0; rr < 5; rr++) {
        int k   = r0 + rr;
        int nid = ev_nids[b * K_ + k];
        int row = nid2rows[b * NI + nid];
        long long gi = (long long)b * NI + row;
        int t = target_idxs[gi];
        const float4* src = reinterpret_cast<const float4*>(
            seq_out + (gi * L_ + t) * (long long)H_);
        reinterpret_cast<float4*>(s_h + k * H_)[lane] = src[lane];
    }
    __syncthreads();

    ull bias0 = ld2(adj_bias + c0);
    ull bias1 = ld2(adj_bias + c1);
    ull acc[5][2];
    #pragma unroll
    for (int r = 0; r < 5; r++) { acc[r][0] = bias0; acc[r][1] = bias1; }

    for (int i = 0; i < K_; i++) {
        ull e0 = ld2(s_h + i * H_ + c0);
        ull e1 = ld2(s_h + i * H_ + c1);
        #pragma unroll
        for (int r = 0; r < 5; r++) {
            ull av = pk2(s_adj[i * K_ + r0 + r]);
            fma2(acc[r][0], av, e0);
            fma2(acc[r][1], av, e1);
        }
    }

    #pragma unroll
    for (int r = 0; r < 5; r++) {
        int gr = b * K_ + r0 + r;
        float2 a0 = upk(acc[r][0]);
        float2 a1 = upk(acc[r][1]);
        *(uint32_t*)(g_x16 + gr * H_ + c0) = f16x2_of(a0.x, a0.y);
        *(uint32_t*)(g_x16 + gr * H_ + c1) = f16x2_of(a1.x, a1.y);

        float2 e0 = upk(ld2(s_h + (r0 + r) * H_ + c0));
        float2 e1 = upk(ld2(s_h + (r0 + r) * H_ + c1));
        *(float2*)(g_h32 + gr * H_ + c0) = e0;
        *(float2*)(g_h32 + gr * H_ + c1) = e1;
        *(uint32_t*)(g_h16 + gr * H_ + c0) = f16x2_of(e0.x, e0.y);
        *(uint32_t*)(g_h16 + gr * H_ + c1) = f16x2_of(e1.x, e1.y);
    }
}

// ---------------------------------------------------------------------------
// K3: one GRU pass, pure fp16 HMMA (1 term).  R10 structure minus wlo.
// Grid (32, 4), 256 threads = 8 warps = 4 col-groups (8 h-cols) x 2 row-groups
// (32 rows).  All 6 gate blocks per warp -> register GRU combine.
// W fragments fully register-resident (96 regs); zero W LDSM in main loop.
// If x == h (pass 2), h fragment loads are skipped (copied from x).
// ---------------------------------------------------------------------------
#define PITCH    272                      /* bytes per A/W smem row */
#define A_TSZ    (64 * PITCH)             /* 17408 */
#define SW_OFF   (2 * A_TSZ)              /* 34816 */
#define W_TSZ    (192 * PITCH)            /* 52224 */
#define HOLD_OFF (SW_OFF + W_TSZ)         /* 87040 */
#define HPITCHB  144                      /* 36 floats, 16B aligned rows */
#define HOLD_SZ  (64 * HPITCHB)           /* 9216 */
#define SMEM_TOT (HOLD_OFF + 2 * HOLD_SZ) /* 105472 */
#define NTILES   5

__global__ __launch_bounds__(256, 1)
void gru_pass_kernel(const __half* __restrict__ x16,
                     const __half* __restrict__ h16,
                     const float* __restrict__ hold,
                     const __half* __restrict__ wih16,
                     const __half* __restrict__ whh16,
                     const float* __restrict__ b_ih,
                     const float* __restrict__ b_hh,
                     float* __restrict__ out32,
                     __half* __restrict__ out16) {
    extern __shared__ __align__(16) char smem[];
    const uint32_t sb  = smem_u32(smem);
    const int tid   = threadIdx.x;
    const int wid   = tid >> 5;
    const int lane  = tid & 31;
    const int ycol0 = blockIdx.y * 32;
    const int m0    = blockIdx.x * NTILES;      // first M-tile
    const bool xh_same = (x16 == h16);

    const int cg    = wid >> 1;            // 0..3 col group (8 h-cols)
    const int rowg  = wid & 1;             // 0..1 row group (32 rows)
    const int mrows = rowg * 32;
    const int gt    = cg * 32 + lane;      // row-group-local tid 0..127

    // ---- per-row-group prefetch: A slices (x16, h16) + hold -----------------
    auto loadA = [&](int m, int pb) {
        {
            const __half* src = x16 + ((size_t)m * 64 + mrows) * H_;
            uint32_t dst = sb + 0 * A_TSZ + mrows * PITCH;
            #pragma unroll
            for (int c = gt; c < 512; c += 128) {       // 32 rows x 16 chunks
                int row = c >> 4, cw = c & 15;
                cp16(dst + row * PITCH + cw * 16, src + row * H_ + cw * 8);
            }
        }
        if (!xh_same) {
            const __half* src = h16 + ((size_t)m * 64 + mrows) * H_;
            uint32_t dst = sb + 1 * A_TSZ + mrows * PITCH;
            #pragma unroll
            for (int c = gt; c < 512; c += 128) {
                int row = c >> 4, cw = c & 15;
                cp16(dst + row * PITCH + cw * 16, src + row * H_ + cw * 8);
            }
        }
        // hold slice: 32 rows x 32 cols f32 (8 chunks/row)
        {
            const float* src = hold + ((size_t)m * 64 + mrows) * H_ + ycol0;
            uint32_t dst = sb + HOLD_OFF + pb * HOLD_SZ + mrows * HPITCHB;
            #pragma unroll
            for (int c = gt; c < 256; c += 128) {       // 32 rows x 8 chunks
                int row = c >> 3, cw = c & 7;
                cp16(dst + row * HPITCHB + cw * 16, src + row * H_ + cw * 4);
            }
        }
    };

    // ---- W load (once): 192 gate-rows x 128 k, fp16 -------------------------
    {
        const __half* wsrc[2] = {wih16, whh16};
        #pragma unroll
        for (int c = tid; c < 3072; c += 256) {         // 192 rows x 16 chunks
            int gp = c >> 4, cw = c & 15;
            int sde = gp / 96, rem = gp % 96;
            int gate = rem >> 5, hc = rem & 31;
            const __half* src = wsrc[sde]
                + (size_t)(gate * H_ + ycol0 + hc) * H_ + cw * 8;
            cp16(sb + SW_OFF + gp * PITCH + cw * 16, src);
        }
    }
    loadA(m0, 0);
    CP_COMMIT();
    CP_WAIT0();
    __syncthreads();                       // W + first A/hold visible

    // ---- fragment address constants -----------------------------------------
    const uint32_t a_lanoff = (uint32_t)(lane & 15) * PITCH
                            + ((lane >> 4) & 1) * 16;
    const int l15 = lane & 15;
    const uint32_t b_lanoff = (uint32_t)(l15 & 7) * PITCH + (l15 >> 3) * 16;

    // W row offset per gate block (0..2: ih r/z/n, 3..5: hh r/z/n)
    uint32_t wrow_off[6];
    #pragma unroll
    for (int blk = 0; blk < 6; blk++) {
        int sde = blk / 3, gate = blk % 3;
        wrow_off[blk] = (uint32_t)(sde * 96 + gate * 32 + cg * 8) * PITCH
                      + b_lanoff;
    }

    // ---- resident weight fragments (96 regs) --------------------------------
    uint32_t bw[8][6][2];
    #pragma unroll
    for (int ks = 0; ks < 8; ks++)
        #pragma unroll
        for (int blk = 0; blk < 6; blk++)
            ldm2(bw[ks][blk], sb + SW_OFF + wrow_off[blk] + ks * 32);

    // ---- epilogue constants (biases hoisted) ---------------------------------
    const int e_colp = ycol0 + cg * 8 + (lane & 3) * 2;   // even col pair base
    const float2 BIr = *(const float2*)(b_ih + e_colp);
    const float2 BIz = *(const float2*)(b_ih + 128 + e_colp);
    const float2 BIn = *(const float2*)(b_ih + 256 + e_colp);
    const float2 BHr = *(const float2*)(b_hh + e_colp);
    const float2 BHz = *(const float2*)(b_hh + 128 + e_colp);
    const float2 BHn = *(const float2*)(b_hh + 256 + e_colp);
    const uint32_t h_lanoff = (uint32_t)(cg * 8 + (lane & 3) * 2) * 4;

    int pb = 0;
    #pragma unroll 1
    for (int it = 0; it < NTILES; it++) {
        const int m     = m0 + it;
        const int mrow0 = m * 64;

        // ---- MMA compute: all 6 gate blocks, single fp16 term -----------------
        float acc[2][6][4];
        #pragma unroll
        for (int mt = 0; mt < 2; mt++)
            #pragma unroll
            for (int j = 0; j < 6; j++)
                #pragma unroll
                for (int q = 0; q < 4; q++) acc[mt][j][q] = 0.0f;

        const uint32_t Ax = sb + 0 * A_TSZ + mrows * PITCH + a_lanoff; // x16
        const uint32_t Ah = sb + 1 * A_TSZ + mrows * PITCH + a_lanoff; // h16

        #pragma unroll
        for (int ks = 0; ks < 8; ks++) {
            uint32_t xf[2][4], hf[2][4];
            ldm4(xf[0], Ax + ks * 32);
            ldm4(xf[1], Ax + ks * 32 + 16 * PITCH);
            if (!xh_same) {
                ldm4(hf[0], Ah + ks * 32);
                ldm4(hf[1], Ah + ks * 32 + 16 * PITCH);
            } else {
                #pragma unroll
                for (int q = 0; q < 4; q++) {
                    hf[0][q] = xf[0][q];
                    hf[1][q] = xf[1][q];
                }
            }

            #pragma unroll
            for (int blk = 0; blk < 6; blk++) {
                const uint32_t* a0 = (blk < 3) ? xf[0] : hf[0];
                const uint32_t* a1 = (blk < 3) ? xf[1] : hf[1];
                hmma(acc[0][blk], a0, bw[ks][blk][0], bw[ks][blk][1]);
                hmma(acc[1][blk], a1, bw[ks][blk][0], bw[ks][blk][1]);
            }
        }
        NB(rowg);                          // row-group's A slice fully consumed

        // ---- prefetch next A + hold (overlaps epilogue) -----------------------
        if (it + 1 < NTILES) { loadA(m + 1, pb ^ 1); CP_COMMIT(); }

        // ---- register epilogue: combine gates -> h' ---------------------------
        const uint32_t hbase = sb + HOLD_OFF + pb * HOLD_SZ + h_lanoff;
        #pragma unroll
        for (int mt = 0; mt < 2; mt++) {
            #pragma unroll
            for (int half = 0; half < 2; half++) {
                int row  = mrows + mt * 16 + (lane >> 2) + half * 8;
                int q0   = half * 2;
                float2 ho = lds2f(hbase + row * HPITCHB);
                float r0 = sigm(acc[mt][0][q0]     + BIr.x + acc[mt][3][q0]     + BHr.x);
                float r1 = sigm(acc[mt][0][q0 + 1] + BIr.y + acc[mt][3][q0 + 1] + BHr.y);
                float z0 = sigm(acc[mt][1][q0]     + BIz.x + acc[mt][4][q0]     + BHz.x);
                float z1 = sigm(acc[mt][1][q0 + 1] + BIz.y + acc[mt][4][q0 + 1] + BHz.y);
                float n0 = tanh_(acc[mt][2][q0]     + BIn.x + r0 * (acc[mt][5][q0]     + BHn.x));
                float n1 = tanh_(acc[mt][2][q0 + 1] + BIn.y + r1 * (acc[mt][5][q0 + 1] + BHn.y));
                float hn0 = (1.0f - z0) * n0 + z0 * ho.x;
                float hn1 = (1.0f - z1) * n1 + z1 * ho.y;
                long long idx = (long long)(mrow0 + row) * H_ + e_colp;
                *(float2*)(out32 + idx) = make_float2(hn0, hn1);
                if (out16)
                    *(uint32_t*)(out16 + idx) = f16x2_of(hn0, hn1);
            }
        }

        if (it + 1 < NTILES) { CP_WAIT0(); }
        NB(rowg);                          // next A/hold ready for row group
        pb ^= 1;
    }
}

// ---------------------------------------------------------------------------
extern "C" void kernel_launch(void* const* d_in, const int* in_sizes, int n_in,
                              void* d_out, int out_size) {
    const float* seq_out     = (const float*)d_in[0];
    const int*   target_idxs = (const int*)  d_in[1];
    const int*   nid2rows    = (const int*)  d_in[2];
    const int*   ev_nids     = (const int*)  d_in[3];
    const float* adj         = (const float*)d_in[4];
    const float* adj_bias    = (const float*)d_in[5];
    const float* w_ih        = (const float*)d_in[6];
    const float* w_hh        = (const float*)d_in[7];
    const float* b_ih        = (const float*)d_in[8];
    const float* b_hh        = (const float*)d_in[9];
    float* out = (float*)d_out;

    static bool attr_set = false;
    if (!attr_set) {
        cudaFuncSetAttribute(gru_pass_kernel,
                             cudaFuncAttributeMaxDynamicSharedMemorySize,
                             SMEM_TOT);
        attr_set = true;
    }

    prep_kernel<<<(GATES * H_ + 255) / 256, 256>>>(w_ih, w_hh);
    gather_adj_kernel<<<B_, 256>>>(seq_out, target_idxs, nid2rows, ev_nids,
                                   adj, adj_bias);

    __half *x16_p, *h16_p, *h216_p, *wih_p, *whh_p;
    float *h32_p, *h232_p;
    cudaGetSymbolAddress((void**)&x16_p,  g_x16);
    cudaGetSymbolAddress((void**)&h16_p,  g_h16);
    cudaGetSymbolAddress((void**)&h216_p, g_h216);
    cudaGetSymbolAddress((void**)&h32_p,  g_h32);
    cudaGetSymbolAddress((void**)&h232_p, g_h232);
    cudaGetSymbolAddress((void**)&wih_p,  g_wih16);
    cudaGetSymbolAddress((void**)&whh_p,  g_whh16);

    dim3 grid(MTOT / (64 * NTILES), 4);    // (32, 4) = 128 CTAs, 1 wave
    // pass 1: x = a, h = ev  -> h1 (fp32 + fp16 into fresh buffers)
    gru_pass_kernel<<<grid, 256, SMEM_TOT>>>(
        x16_p, h16_p, h32_p,
        wih_p, whh_p, b_ih, b_hh,
        h232_p, h216_p);
    // pass 2: x = h = h1 (same pointer -> A loads halved) -> d_out
    gru_pass_kernel<<<grid, 256, SMEM_TOT>>>(
        h216_p, h216_p, h232_p,
        wih_p, whh_p, b_ih, b_hh,
        out, nullptr);
}

// round 14
// speedup vs baseline: 1.4377x; 1.0045x over previous
#include <cuda_runtime.h>
#include <cuda_fp16.h>
#include <cstdint>

#define B_    256
#define NI    64
#define L_    128
#define H_    128
#define K_    40
#define MTOT  (B_ * K_)          /* 10240 rows */
#define GATES 384

typedef unsigned long long ull;

// ---------------------------------------------------------------------------
// Device scratch (fp16 activations/weights; fp32 hold state)
// ---------------------------------------------------------------------------
__device__ __align__(256) __half g_x16[MTOT * H_];
__device__ __align__(256) __half g_h16[MTOT * H_];
__device__ __align__(256) float  g_h32[MTOT * H_];
__device__ __align__(256) __half g_h216[MTOT * H_];
__device__ __align__(256) float  g_h232[MTOT * H_];
__device__ __align__(256) __half g_wih16[GATES * H_];
__device__ __align__(256) __half g_whh16[GATES * H_];

// ---------------------------------------------------------------------------
// Helpers
// ---------------------------------------------------------------------------
__device__ __forceinline__ uint32_t smem_u32(const void* p) {
    uint32_t a;
    asm("{ .reg .u64 t; cvta.to.shared.u64 t, %1; cvt.u32.u64 %0, t; }"
        : "=r"(a) : "l"(p));
    return a;
}
__device__ __forceinline__ void cp16(uint32_t dst, const void* src) {
    asm volatile("cp.async.cg.shared.global [%0], [%1], 16;"
                 :: "r"(dst), "l"(src) : "memory");
}
#define CP_COMMIT() asm volatile("cp.async.commit_group;" ::: "memory")
#define CP_WAIT0()  asm volatile("cp.async.wait_group 0;" ::: "memory")
#define NB(id)      asm volatile("bar.sync %0, 128;" :: "r"((id) + 1) : "memory")

__device__ __forceinline__ void ldm4(uint32_t* a, uint32_t addr) {
    asm volatile("ldmatrix.sync.aligned.m8n8.x4.shared.b16 {%0,%1,%2,%3}, [%4];"
                 : "=r"(a[0]), "=r"(a[1]), "=r"(a[2]), "=r"(a[3]) : "r"(addr));
}
__device__ __forceinline__ void ldm2(uint32_t* a, uint32_t addr) {
    asm volatile("ldmatrix.sync.aligned.m8n8.x2.shared.b16 {%0,%1}, [%2];"
                 : "=r"(a[0]), "=r"(a[1]) : "r"(addr));
}
__device__ __forceinline__ float2 lds2f(uint32_t addr) {
    float2 v;
    asm volatile("ld.shared.v2.f32 {%0,%1}, [%2];"
                 : "=f"(v.x), "=f"(v.y) : "r"(addr));
    return v;
}
__device__ __forceinline__ void hmma(float* c, const uint32_t* a,
                                     uint32_t b0, uint32_t b1) {
    asm volatile("mma.sync.aligned.m16n8k16.row.col.f32.f16.f16.f32 "
                 "{%0,%1,%2,%3}, {%4,%5,%6,%7}, {%8,%9}, {%0,%1,%2,%3};"
                 : "+f"(c[0]), "+f"(c[1]), "+f"(c[2]), "+f"(c[3])
                 : "r"(a[0]), "r"(a[1]), "r"(a[2]), "r"(a[3]),
                   "r"(b0), "r"(b1));
}

__device__ __forceinline__ ull pk2(float v) {
    ull r; asm("mov.b64 %0, {%1, %1};" : "=l"(r) : "f"(v)); return r;
}
__device__ __forceinline__ float2 upk(ull v) {
    float2 f; asm("mov.b64 {%0, %1}, %2;" : "=f"(f.x), "=f"(f.y) : "l"(v)); return f;
}
__device__ __forceinline__ void fma2(ull& d, ull a, ull b) {
    asm("fma.rn.f32x2 %0, %1, %2, %0;" : "+l"(d) : "l"(a), "l"(b));
}
__device__ __forceinline__ ull ld2(const float* p) { return *(const ull*)p; }

__device__ __forceinline__ float sigm(float x) {
    return __fdividef(1.0f, 1.0f + __expf(-x));
}
__device__ __forceinline__ float tanh_(float x) {
    return __fdividef(2.0f, 1.0f + __expf(-2.0f * x)) - 1.0f;
}
// pack two floats into f16x2 (lo = a, hi = b)
__device__ __forceinline__ uint32_t f16x2_of(float a, float b) {
    uint32_t r;
    asm("cvt.rn.f16x2.f32 %0, %1, %2;" : "=r"(r) : "f"(b), "f"(a));
    return r;
}

// ---------------------------------------------------------------------------
// K1: convert weights to fp16
// ---------------------------------------------------------------------------
__global__ void prep_kernel(const float* __restrict__ w_ih,
                            const float* __restrict__ w_hh) {
    int idx = blockIdx.x * blockDim.x + threadIdx.x;
    if (idx < GATES * H_) {
        g_wih16[idx] = __float2half(w_ih[idx]);
        g_whh16[idx] = __float2half(w_hh[idx]);
    }
}

// ---------------------------------------------------------------------------
// K2: gather + adj GEMM -> x (a) fp16, h (ev) fp16 + fp32 hold.
// ---------------------------------------------------------------------------
__global__ __launch_bounds__(256, 1)
void gather_adj_kernel(const float* __restrict__ seq_out,
                       const int*   __restrict__ target_idxs,
                       const int*   __restrict__ nid2rows,
                       const int*   __restrict__ ev_nids,
                       const float* __restrict__ adj,
                       const float* __restrict__ adj_bias) {
    __shared__ float s_h[K_ * H_];
    __shared__ float s_adj[K_ * K_];

    const int b    = blockIdx.x;
    const int tid  = threadIdx.x;
    const int warp = tid >> 5;
    const int lane = tid & 31;
    const int r0   = warp * 5;
    const int c0   = lane * 2;
    const int c1   = lane * 2 + 64;

    for (int i = tid; i < K_ * K_; i += 256)
        s_adj[i] = adj[b * K_ * K_ + i];

    #pragma unroll
    for (int rr = 0; rr < 5; rr++) {
        int k   = r0 + rr;
        int nid = ev_nids[b * K_ + k];
        int row = nid2rows[b * NI + nid];
        long long gi = (long long)b * NI + row;
        int t = target_idxs[gi];
        const float4* src = reinterpret_cast<const float4*>(
            seq_out + (gi * L_ + t) * (long long)H_);
        reinterpret_cast<float4*>(s_h + k * H_)[lane] = src[lane];
    }
    __syncthreads();

    ull bias0 = ld2(adj_bias + c0);
    ull bias1 = ld2(adj_bias + c1);
    ull acc[5][2];
    #pragma unroll
    for (int r = 0; r < 5; r++) { acc[r][0] = bias0; acc[r][1] = bias1; }

    for (int i = 0; i < K_; i++) {
        ull e0 = ld2(s_h + i * H_ + c0);
        ull e1 = ld2(s_h + i * H_ + c1);
        #pragma unroll
        for (int r = 0; r < 5; r++) {
            ull av = pk2(s_adj[i * K_ + r0 + r]);
            fma2(acc[r][0], av, e0);
            fma2(acc[r][1], av, e1);
        }
    }

    #pragma unroll
    for (int r = 0; r < 5; r++) {
        int gr = b * K_ + r0 + r;
        float2 a0 = upk(acc[r][0]);
        float2 a1 = upk(acc[r][1]);
        *(uint32_t*)(g_x16 + gr * H_ + c0) = f16x2_of(a0.x, a0.y);
        *(uint32_t*)(g_x16 + gr * H_ + c1) = f16x2_of(a1.x, a1.y);

        float2 e0 = upk(ld2(s_h + (r0 + r) * H_ + c0));
        float2 e1 = upk(ld2(s_h + (r0 + r) * H_ + c1));
        *(float2*)(g_h32 + gr * H_ + c0) = e0;
        *(float2*)(g_h32 + gr * H_ + c1) = e1;
        *(uint32_t*)(g_h16 + gr * H_ + c0) = f16x2_of(e0.x, e0.y);
        *(uint32_t*)(g_h16 + gr * H_ + c1) = f16x2_of(e1.x, e1.y);
    }
}

// ---------------------------------------------------------------------------
// K3: one GRU pass, pure fp16 HMMA (1 term), A double-buffered.
// Grid (32, 4), 256 threads = 8 warps = 4 col-groups (8 h-cols) x 2 row-groups
// (32 rows).  All 6 gate blocks per warp -> register GRU combine.
// W fragments fully register-resident (96 regs); zero W LDSM in main loop.
// Next tile's A + hold prefetch issued BEFORE compute -> covered by the whole
// tile; ONE named barrier per tile.  If x == h (pass 2), h loads skipped.
// ---------------------------------------------------------------------------
#define PITCH    272                      /* bytes per A/W smem row */
#define A_TSZ    (64 * PITCH)             /* 17408 */
#define SW_OFF   (4 * A_TSZ)              /* 69632: 2 bufs x (x,h) */
#define W_TSZ    (192 * PITCH)            /* 52224 */
#define HOLD_OFF (SW_OFF + W_TSZ)         /* 121856 */
#define HPITCHB  144                      /* 36 floats, 16B aligned rows */
#define HOLD_SZ  (64 * HPITCHB)           /* 9216 */
#define SMEM_TOT (HOLD_OFF + 2 * HOLD_SZ) /* 140288 */
#define NTILES   5

__global__ __launch_bounds__(256, 1)
void gru_pass_kernel(const __half* __restrict__ x16,
                     const __half* __restrict__ h16,
                     const float* __restrict__ hold,
                     const __half* __restrict__ wih16,
                     const __half* __restrict__ whh16,
                     const float* __restrict__ b_ih,
                     const float* __restrict__ b_hh,
                     float* __restrict__ out32,
                     __half* __restrict__ out16) {
    extern __shared__ __align__(16) char smem[];
    const uint32_t sb  = smem_u32(smem);
    const int tid   = threadIdx.x;
    const int wid   = tid >> 5;
    const int lane  = tid & 31;
    const int ycol0 = blockIdx.y * 32;
    const int m0    = blockIdx.x * NTILES;      // first M-tile
    const bool xh_same = (x16 == h16);

    const int cg    = wid >> 1;            // 0..3 col group (8 h-cols)
    const int rowg  = wid & 1;             // 0..1 row group (32 rows)
    const int mrows = rowg * 32;
    const int gt    = cg * 32 + lane;      // row-group-local tid 0..127

    // ---- per-row-group prefetch: A slices (x16, h16) + hold into buf pb -----
    auto loadA = [&](int m, int pb) {
        {
            const __half* src = x16 + ((size_t)m * 64 + mrows) * H_;
            uint32_t dst = sb + (pb * 2 + 0) * A_TSZ + mrows * PITCH;
            #pragma unroll
            for (int c = gt; c < 512; c += 128) {       // 32 rows x 16 chunks
                int row = c >> 4, cw = c & 15;
                cp16(dst + row * PITCH + cw * 16, src + row * H_ + cw * 8);
            }
        }
        if (!xh_same) {
            const __half* src = h16 + ((size_t)m * 64 + mrows) * H_;
            uint32_t dst = sb + (pb * 2 + 1) * A_TSZ + mrows * PITCH;
            #pragma unroll
            for (int c = gt; c < 512; c += 128) {
                int row = c >> 4, cw = c & 15;
                cp16(dst + row * PITCH + cw * 16, src + row * H_ + cw * 8);
            }
        }
        // hold slice: 32 rows x 32 cols f32 (8 chunks/row)
        {
            const float* src = hold + ((size_t)m * 64 + mrows) * H_ + ycol0;
            uint32_t dst = sb + HOLD_OFF + pb * HOLD_SZ + mrows * HPITCHB;
            #pragma unroll
            for (int c = gt; c < 256; c += 128) {       // 32 rows x 8 chunks
                int row = c >> 3, cw = c & 7;
                cp16(dst + row * HPITCHB + cw * 16, src + row * H_ + cw * 4);
            }
        }
    };

    // ---- W load (once): 192 gate-rows x 128 k, fp16 -------------------------
    {
        const __half* wsrc[2] = {wih16, whh16};
        #pragma unroll
        for (int c = tid; c < 3072; c += 256) {         // 192 rows x 16 chunks
            int gp = c >> 4, cw = c & 15;
            int sde = gp / 96, rem = gp % 96;
            int gate = rem >> 5, hc = rem & 31;
            const __half* src = wsrc[sde]
                + (size_t)(gate * H_ + ycol0 + hc) * H_ + cw * 8;
            cp16(sb + SW_OFF + gp * PITCH + cw * 16, src);
        }
    }
    loadA(m0, 0);
    CP_COMMIT();
    CP_WAIT0();
    __syncthreads();                       // W + first A/hold visible

    // ---- fragment address constants -----------------------------------------
    const uint32_t a_lanoff = (uint32_t)(lane & 15) * PITCH
                            + ((lane >> 4) & 1) * 16;
    const int l15 = lane & 15;
    const uint32_t b_lanoff = (uint32_t)(l15 & 7) * PITCH + (l15 >> 3) * 16;

    // W row offset per gate block (0..2: ih r/z/n, 3..5: hh r/z/n)
    uint32_t wrow_off[6];
    #pragma unroll
    for (int blk = 0; blk < 6; blk++) {
        int sde = blk / 3, gate = blk % 3;
        wrow_off[blk] = (uint32_t)(sde * 96 + gate * 32 + cg * 8) * PITCH
                      + b_lanoff;
    }

    // ---- resident weight fragments (96 regs) --------------------------------
    uint32_t bw[8][6][2];
    #pragma unroll
    for (int ks = 0; ks < 8; ks++)
        #pragma unroll
        for (int blk = 0; blk < 6; blk++)
            ldm2(bw[ks][blk], sb + SW_OFF + wrow_off[blk] + ks * 32);

    // ---- epilogue constants (biases hoisted) ---------------------------------
    const int e_colp = ycol0 + cg * 8 + (lane & 3) * 2;   // even col pair base
    const float2 BIr = *(const float2*)(b_ih + e_colp);
    const float2 BIz = *(const float2*)(b_ih + 128 + e_colp);
    const float2 BIn = *(const float2*)(b_ih + 256 + e_colp);
    const float2 BHr = *(const float2*)(b_hh + e_colp);
    const float2 BHz = *(const float2*)(b_hh + 128 + e_colp);
    const float2 BHn = *(const float2*)(b_hh + 256 + e_colp);
    const uint32_t h_lanoff = (uint32_t)(cg * 8 + (lane & 3) * 2) * 4;

    int pb = 0;
    #pragma unroll 1
    for (int it = 0; it < NTILES; it++) {
        const int m     = m0 + it;
        const int mrow0 = m * 64;

        // ---- prefetch NEXT tile's A + hold first (covered by whole tile) ------
        if (it + 1 < NTILES) { loadA(m + 1, pb ^ 1); CP_COMMIT(); }

        // ---- MMA compute: all 6 gate blocks, single fp16 term -----------------
        float acc[2][6][4];
        #pragma unroll
        for (int mt = 0; mt < 2; mt++)
            #pragma unroll
            for (int j = 0; j < 6; j++)
                #pragma unroll
                for (int q = 0; q < 4; q++) acc[mt][j][q] = 0.0f;

        const uint32_t Ax = sb + (pb * 2 + 0) * A_TSZ + mrows * PITCH + a_lanoff;
        const uint32_t Ah = sb + (pb * 2 + 1) * A_TSZ + mrows * PITCH + a_lanoff;

        #pragma unroll
        for (int ks = 0; ks < 8; ks++) {
            uint32_t xf[2][4], hf[2][4];
            ldm4(xf[0], Ax + ks * 32);
            ldm4(xf[1], Ax + ks * 32 + 16 * PITCH);
            if (!xh_same) {
                ldm4(hf[0], Ah + ks * 32);
                ldm4(hf[1], Ah + ks * 32 + 16 * PITCH);
            } else {
                #pragma unroll
                for (int q = 0; q < 4; q++) {
                    hf[0][q] = xf[0][q];
                    hf[1][q] = xf[1][q];
                }
            }

            #pragma unroll
            for (int blk = 0; blk < 6; blk++) {
                const uint32_t* a0 = (blk < 3) ? xf[0] : hf[0];
                const uint32_t* a1 = (blk < 3) ? xf[1] : hf[1];
                hmma(acc[0][blk], a0, bw[ks][blk][0], bw[ks][blk][1]);
                hmma(acc[1][blk], a1, bw[ks][blk][0], bw[ks][blk][1]);
            }
        }

        // ---- register epilogue: combine gates -> h' ---------------------------
        const uint32_t hbase = sb + HOLD_OFF + pb * HOLD_SZ + h_lanoff;
        #pragma unroll
        for (int mt = 0; mt < 2; mt++) {
            #pragma unroll
            for (int half = 0; half < 2; half++) {
                int row  = mrows + mt * 16 + (lane >> 2) + half * 8;
                int q0   = half * 2;
                float2 ho = lds2f(hbase + row * HPITCHB);
                float r0 = sigm(acc[mt][0][q0]     + BIr.x + acc[mt][3][q0]     + BHr.x);
                float r1 = sigm(acc[mt][0][q0 + 1] + BIr.y + acc[mt][3][q0 + 1] + BHr.y);
                float z0 = sigm(acc[mt][1][q0]     + BIz.x + acc[mt][4][q0]     + BHz.x);
                float z1 = sigm(acc[mt][1][q0 + 1] + BIz.y + acc[mt][4][q0 + 1] + BHz.y);
                float n0 = tanh_(acc[mt][2][q0]     + BIn.x + r0 * (acc[mt][5][q0]     + BHn.x));
                float n1 = tanh_(acc[mt][2][q0 + 1] + BIn.y + r1 * (acc[mt][5][q0 + 1] + BHn.y));
                float hn0 = (1.0f - z0) * n0 + z0 * ho.x;
                float hn1 = (1.0f - z1) * n1 + z1 * ho.y;
                long long idx = (long long)(mrow0 + row) * H_ + e_colp;
                *(float2*)(out32 + idx) = make_float2(hn0, hn1);
                if (out16)
                    *(uint32_t*)(out16 + idx) = f16x2_of(hn0, hn1);
            }
        }

        // ---- close the tile: wait for next A, one barrier ----------------------
        if (it + 1 < NTILES) {
            CP_WAIT0();
            NB(rowg);
        }
        pb ^= 1;
    }
}

// ---------------------------------------------------------------------------
extern "C" void kernel_launch(void* const* d_in, const int* in_sizes, int n_in,
                              void* d_out, int out_size) {
    const float* seq_out     = (const float*)d_in[0];
    const int*   target_idxs = (const int*)  d_in[1];
    const int*   nid2rows    = (const int*)  d_in[2];
    const int*   ev_nids     = (const int*)  d_in[3];
    const float* adj         = (const float*)d_in[4];
    const float* adj_bias    = (const float*)d_in[5];
    const float* w_ih        = (const float*)d_in[6];
    const float* w_hh        = (const float*)d_in[7];
    const float* b_ih        = (const float*)d_in[8];
    const float* b_hh        = (const float*)d_in[9];
    float* out = (float*)d_out;

    static bool attr_set = false;
    if (!attr_set) {
        cudaFuncSetAttribute(gru_pass_kernel,
                             cudaFuncAttributeMaxDynamicSharedMemorySize,
                             SMEM_TOT);
        attr_set = true;
    }

    prep_kernel<<<(GATES * H_ + 255) / 256, 256>>>(w_ih, w_hh);
    gather_adj_kernel<<<B_, 256>>>(seq_out, target_idxs, nid2rows, ev_nids,
                                   adj, adj_bias);

    __half *x16_p, *h16_p, *h216_p, *wih_p, *whh_p;
    float *h32_p, *h232_p;
    cudaGetSymbolAddress((void**)&x16_p,  g_x16);
    cudaGetSymbolAddress((void**)&h16_p,  g_h16);
    cudaGetSymbolAddress((void**)&h216_p, g_h216);
    cudaGetSymbolAddress((void**)&h32_p,  g_h32);
    cudaGetSymbolAddress((void**)&h232_p, g_h232);
    cudaGetSymbolAddress((void**)&wih_p,  g_wih16);
    cudaGetSymbolAddress((void**)&whh_p,  g_whh16);

    dim3 grid(MTOT / (64 * NTILES), 4);    // (32, 4) = 128 CTAs, 1 wave
    // pass 1: x = a, h = ev  -> h1 (fp32 + fp16 into fresh buffers)
    gru_pass_kernel<<<grid, 256, SMEM_TOT>>>(
        x16_p, h16_p, h32_p,
        wih_p, whh_p, b_ih, b_hh,
        h232_p, h216_p);
    // pass 2: x = h = h1 (same pointer -> A loads halved) -> d_out
    gru_pass_kernel<<<grid, 256, SMEM_TOT>>>(
        h216_p, h216_p, h232_p,
        wih_p, whh_p, b_ih, b_hh,
        out, nullptr);
}

// round 16
// speedup vs baseline: 1.6205x; 1.1272x over previous
#include <cuda_runtime.h>
#include <cuda_fp16.h>
#include <cstdint>

#define B_    256
#define NI    64
#define L_    128
#define H_    128
#define K_    40
#define MTOT  (B_ * K_)          /* 10240 rows */
#define GATES 384

typedef unsigned long long ull;

// ---------------------------------------------------------------------------
// Device scratch (fp16 activations/weights)
// ---------------------------------------------------------------------------
__device__ __align__(256) __half g_x16[MTOT * H_];
__device__ __align__(256) __half g_h16[MTOT * H_];
__device__ __align__(256) __half g_h216[MTOT * H_];
__device__ __align__(256) __half g_wih16[GATES * H_];
__device__ __align__(256) __half g_whh16[GATES * H_];

// ---------------------------------------------------------------------------
// Helpers
// ---------------------------------------------------------------------------
__device__ __forceinline__ uint32_t smem_u32(const void* p) {
    uint32_t a;
    asm("{ .reg .u64 t; cvta.to.shared.u64 t, %1; cvt.u32.u64 %0, t; }"
        : "=r"(a) : "l"(p));
    return a;
}
__device__ __forceinline__ void cp16(uint32_t dst, const void* src) {
    asm volatile("cp.async.cg.shared.global [%0], [%1], 16;"
                 :: "r"(dst), "l"(src) : "memory");
}
#define CP_COMMIT() asm volatile("cp.async.commit_group;" ::: "memory")
#define CP_WAIT0()  asm volatile("cp.async.wait_group 0;" ::: "memory")
#define NB(id)      asm volatile("bar.sync %0, 128;" :: "r"((id) + 1) : "memory")

__device__ __forceinline__ void ldm4(uint32_t* a, uint32_t addr) {
    asm volatile("ldmatrix.sync.aligned.m8n8.x4.shared.b16 {%0,%1,%2,%3}, [%4];"
                 : "=r"(a[0]), "=r"(a[1]), "=r"(a[2]), "=r"(a[3]) : "r"(addr));
}
__device__ __forceinline__ void ldm2(uint32_t* a, uint32_t addr) {
    asm volatile("ldmatrix.sync.aligned.m8n8.x2.shared.b16 {%0,%1}, [%2];"
                 : "=r"(a[0]), "=r"(a[1]) : "r"(addr));
}
__device__ __forceinline__ uint32_t ldsu(uint32_t addr) {
    uint32_t v;
    asm volatile("ld.shared.b32 %0, [%1];" : "=r"(v) : "r"(addr));
    return v;
}
__device__ __forceinline__ void hmma(float* c, const uint32_t* a,
                                     uint32_t b0, uint32_t b1) {
    asm volatile("mma.sync.aligned.m16n8k16.row.col.f32.f16.f16.f32 "
                 "{%0,%1,%2,%3}, {%4,%5,%6,%7}, {%8,%9}, {%0,%1,%2,%3};"
                 : "+f"(c[0]), "+f"(c[1]), "+f"(c[2]), "+f"(c[3])
                 : "r"(a[0]), "r"(a[1]), "r"(a[2]), "r"(a[3]),
                   "r"(b0), "r"(b1));
}

__device__ __forceinline__ ull pk2(float v) {
    ull r; asm("mov.b64 %0, {%1, %1};" : "=l"(r) : "f"(v)); return r;
}
__device__ __forceinline__ float2 upk(ull v) {
    float2 f; asm("mov.b64 {%0, %1}, %2;" : "=f"(f.x), "=f"(f.y) : "l"(v)); return f;
}
__device__ __forceinline__ void fma2(ull& d, ull a, ull b) {
    asm("fma.rn.f32x2 %0, %1, %2, %0;" : "+l"(d) : "l"(a), "l"(b));
}
__device__ __forceinline__ ull ld2(const float* p) { return *(const ull*)p; }

__device__ __forceinline__ float tanhap(float x) {
    float y; asm("tanh.approx.f32 %0, %1;" : "=f"(y) : "f"(x)); return y;
}
__device__ __forceinline__ float sigm(float x) {
    return fmaf(tanhap(0.5f * x), 0.5f, 0.5f);
}
// pack two floats into f16x2 (lo = a, hi = b)
__device__ __forceinline__ uint32_t f16x2_of(float a, float b) {
    uint32_t r;
    asm("cvt.rn.f16x2.f32 %0, %1, %2;" : "=r"(r) : "f"(b), "f"(a));
    return r;
}

// ---------------------------------------------------------------------------
// K1: gather + adj GEMM -> x (a) fp16, h (ev) fp16.  Also converts the GRU
// weights to fp16 (prep folded in: idx = b*256 + tid covers both matrices).
// ---------------------------------------------------------------------------
__global__ __launch_bounds__(256, 1)
void gather_adj_kernel(const float* __restrict__ seq_out,
                       const int*   __restrict__ target_idxs,
                       const int*   __restrict__ nid2rows,
                       const int*   __restrict__ ev_nids,
                       const float* __restrict__ adj,
                       const float* __restrict__ adj_bias,
                       const float* __restrict__ w_ih,
                       const float* __restrict__ w_hh) {
    __shared__ float s_h[K_ * H_];
    __shared__ float s_adj[K_ * K_];

    const int b    = blockIdx.x;
    const int tid  = threadIdx.x;
    const int warp = tid >> 5;
    const int lane = tid & 31;
    const int r0   = warp * 5;
    const int c0   = lane * 2;
    const int c1   = lane * 2 + 64;

    // folded prep: 256 blocks x 256 threads cover all 49152 W elements
    {
        int idx = b * 256 + tid;
        if (idx < GATES * H_) {
            g_wih16[idx] = __float2half(w_ih[idx]);
            g_whh16[idx] = __float2half(w_hh[idx]);
        }
    }

    for (int i = tid; i < K_ * K_; i += 256)
        s_adj[i] = adj[b * K_ * K_ + i];

    #pragma unroll
    for (int rr = 0; rr < 5; rr++) {
        int k   = r0 + rr;
        int nid = ev_nids[b * K_ + k];
        int row = nid2rows[b * NI + nid];
        long long gi = (long long)b * NI + row;
        int t = target_idxs[gi];
        const float4* src = reinterpret_cast<const float4*>(
            seq_out + (gi * L_ + t) * (long long)H_);
        reinterpret_cast<float4*>(s_h + k * H_)[lane] = src[lane];
    }
    __syncthreads();

    ull bias0 = ld2(adj_bias + c0);
    ull bias1 = ld2(adj_bias + c1);
    ull acc[5][2];
    #pragma unroll
    for (int r = 0; r < 5; r++) { acc[r][0] = bias0; acc[r][1] = bias1; }

    for (int i = 0; i < K_; i++) {
        ull e0 = ld2(s_h + i * H_ + c0);
        ull e1 = ld2(s_h + i * H_ + c1);
        #pragma unroll
        for (int r = 0; r < 5; r++) {
            ull av = pk2(s_adj[i * K_ + r0 + r]);
            fma2(acc[r][0], av, e0);
            fma2(acc[r][1], av, e1);
        }
    }

    #pragma unroll
    for (int r = 0; r < 5; r++) {
        int gr = b * K_ + r0 + r;
        float2 a0 = upk(acc[r][0]);
        float2 a1 = upk(acc[r][1]);
        *(uint32_t*)(g_x16 + gr * H_ + c0) = f16x2_of(a0.x, a0.y);
        *(uint32_t*)(g_x16 + gr * H_ + c1) = f16x2_of(a1.x, a1.y);

        float2 e0 = upk(ld2(s_h + (r0 + r) * H_ + c0));
        float2 e1 = upk(ld2(s_h + (r0 + r) * H_ + c1));
        *(uint32_t*)(g_h16 + gr * H_ + c0) = f16x2_of(e0.x, e0.y);
        *(uint32_t*)(g_h16 + gr * H_ + c1) = f16x2_of(e1.x, e1.y);
    }
}

// ---------------------------------------------------------------------------
// K2: one GRU pass, pure fp16 HMMA, A double-buffered, fp16 hold.
// Grid (32, 4), 256 threads = 8 warps = 4 col-groups (8 h-cols) x 2 row-groups
// (32 rows).  All 6 gate blocks per warp -> register GRU combine with
// tanh.approx gates.  W fragments register-resident; hold read from the h16
// smem A-tile (no fp32 side channel).  One barrier per tile.
// ---------------------------------------------------------------------------
#define PITCH    272                      /* bytes per A/W smem row */
#define A_TSZ    (64 * PITCH)             /* 17408 */
#define SW_OFF   (4 * A_TSZ)              /* 69632: 2 bufs x (x,h) */
#define W_TSZ    (192 * PITCH)            /* 52224 */
#define SMEM_TOT (SW_OFF + W_TSZ)         /* 121856 */
#define NTILES   5

__global__ __launch_bounds__(256, 1)
void gru_pass_kernel(const __half* __restrict__ x16,
                     const __half* __restrict__ h16,
                     const __half* __restrict__ wih16,
                     const __half* __restrict__ whh16,
                     const float* __restrict__ b_ih,
                     const float* __restrict__ b_hh,
                     float* __restrict__ out32,
                     __half* __restrict__ out16) {
    extern __shared__ __align__(16) char smem[];
    const uint32_t sb  = smem_u32(smem);
    const int tid   = threadIdx.x;
    const int wid   = tid >> 5;
    const int lane  = tid & 31;
    const int ycol0 = blockIdx.y * 32;
    const int m0    = blockIdx.x * NTILES;      // first M-tile
    const bool xh_same = (x16 == h16);

    const int cg    = wid >> 1;            // 0..3 col group (8 h-cols)
    const int rowg  = wid & 1;             // 0..1 row group (32 rows)
    const int mrows = rowg * 32;
    const int gt    = cg * 32 + lane;      // row-group-local tid 0..127

    // ---- per-row-group prefetch: A slices (x16, h16) into buf pb ------------
    auto loadA = [&](int m, int pb) {
        {
            const __half* src = x16 + ((size_t)m * 64 + mrows) * H_;
            uint32_t dst = sb + (pb * 2 + 0) * A_TSZ + mrows * PITCH;
            #pragma unroll
            for (int c = gt; c < 512; c += 128) {       // 32 rows x 16 chunks
                int row = c >> 4, cw = c & 15;
                cp16(dst + row * PITCH + cw * 16, src + row * H_ + cw * 8);
            }
        }
        if (!xh_same) {
            const __half* src = h16 + ((size_t)m * 64 + mrows) * H_;
            uint32_t dst = sb + (pb * 2 + 1) * A_TSZ + mrows * PITCH;
            #pragma unroll
            for (int c = gt; c < 512; c += 128) {
                int row = c >> 4, cw = c & 15;
                cp16(dst + row * PITCH + cw * 16, src + row * H_ + cw * 8);
            }
        }
    };

    // ---- W load (once): 192 gate-rows x 128 k, fp16 -------------------------
    {
        const __half* wsrc[2] = {wih16, whh16};
        #pragma unroll
        for (int c = tid; c < 3072; c += 256) {         // 192 rows x 16 chunks
            int gp = c >> 4, cw = c & 15;
            int sde = gp / 96, rem = gp % 96;
            int gate = rem >> 5, hc = rem & 31;
            const __half* src = wsrc[sde]
                + (size_t)(gate * H_ + ycol0 + hc) * H_ + cw * 8;
            cp16(sb + SW_OFF + gp * PITCH + cw * 16, src);
        }
    }
    loadA(m0, 0);
    CP_COMMIT();
    CP_WAIT0();
    __syncthreads();                       // W + first A visible

    // ---- fragment address constants -----------------------------------------
    const uint32_t a_lanoff = (uint32_t)(lane & 15) * PITCH
                            + ((lane >> 4) & 1) * 16;
    const int l15 = lane & 15;
    const uint32_t b_lanoff = (uint32_t)(l15 & 7) * PITCH + (l15 >> 3) * 16;

    // W row offset per gate block (0..2: ih r/z/n, 3..5: hh r/z/n)
    uint32_t wrow_off[6];
    #pragma unroll
    for (int blk = 0; blk < 6; blk++) {
        int sde = blk / 3, gate = blk % 3;
        wrow_off[blk] = (uint32_t)(sde * 96 + gate * 32 + cg * 8) * PITCH
                      + b_lanoff;
    }

    // ---- resident weight fragments (96 regs) --------------------------------
    uint32_t bw[8][6][2];
    #pragma unroll
    for (int ks = 0; ks < 8; ks++)
        #pragma unroll
        for (int blk = 0; blk < 6; blk++)
            ldm2(bw[ks][blk], sb + SW_OFF + wrow_off[blk] + ks * 32);

    // ---- epilogue constants (biases hoisted) ---------------------------------
    const int e_colp = ycol0 + cg * 8 + (lane & 3) * 2;   // even col pair base
    const float2 BIr = *(const float2*)(b_ih + e_colp);
    const float2 BIz = *(const float2*)(b_ih + 128 + e_colp);
    const float2 BIn = *(const float2*)(b_ih + 256 + e_colp);
    const float2 BHr = *(const float2*)(b_hh + e_colp);
    const float2 BHz = *(const float2*)(b_hh + 128 + e_colp);
    const float2 BHn = *(const float2*)(b_hh + 256 + e_colp);
    // hold = h16 A-tile element at (row, e_colp): byte offset within tile
    const uint32_t ho_lanoff = (uint32_t)e_colp * 2;

    int pb = 0;
    #pragma unroll 1
    for (int it = 0; it < NTILES; it++) {
        const int m     = m0 + it;
        const int mrow0 = m * 64;

        // ---- prefetch NEXT tile's A first (covered by whole tile) --------------
        if (it + 1 < NTILES) { loadA(m + 1, pb ^ 1); CP_COMMIT(); }

        // ---- MMA compute: all 6 gate blocks, single fp16 term -----------------
        float acc[2][6][4];
        #pragma unroll
        for (int mt = 0; mt < 2; mt++)
            #pragma unroll
            for (int j = 0; j < 6; j++)
                #pragma unroll
                for (int q = 0; q < 4; q++) acc[mt][j][q] = 0.0f;

        const uint32_t Ax = sb + (pb * 2 + 0) * A_TSZ + mrows * PITCH + a_lanoff;
        const uint32_t Ah = sb + (pb * 2 + 1) * A_TSZ + mrows * PITCH + a_lanoff;

        #pragma unroll
        for (int ks = 0; ks < 8; ks++) {
            uint32_t xf[2][4], hf[2][4];
            ldm4(xf[0], Ax + ks * 32);
            ldm4(xf[1], Ax + ks * 32 + 16 * PITCH);
            if (!xh_same) {
                ldm4(hf[0], Ah + ks * 32);
                ldm4(hf[1], Ah + ks * 32 + 16 * PITCH);
            } else {
                #pragma unroll
                for (int q = 0; q < 4; q++) {
                    hf[0][q] = xf[0][q];
                    hf[1][q] = xf[1][q];
                }
            }

            #pragma unroll
            for (int blk = 0; blk < 6; blk++) {
                const uint32_t* a0 = (blk < 3) ? xf[0] : hf[0];
                const uint32_t* a1 = (blk < 3) ? xf[1] : hf[1];
                hmma(acc[0][blk], a0, bw[ks][blk][0], bw[ks][blk][1]);
                hmma(acc[1][blk], a1, bw[ks][blk][0], bw[ks][blk][1]);
            }
        }

        // ---- register epilogue: combine gates -> h' ---------------------------
        // hold read from the h16 (or x16 when aliased) smem A-tile, fp16.
        const uint32_t HoBase = sb + (pb * 2 + (xh_same ? 0 : 1)) * A_TSZ
                              + ho_lanoff;
        #pragma unroll
        for (int mt = 0; mt < 2; mt++) {
            #pragma unroll
            for (int half = 0; half < 2; half++) {
                int row  = mrows + mt * 16 + (lane >> 2) + half * 8;
                int q0   = half * 2;
                uint32_t hop = ldsu(HoBase + row * PITCH);
                float2 ho = __half22float2(*reinterpret_cast<__half2*>(&hop));
                float r0 = sigm(acc[mt][0][q0]     + BIr.x + acc[mt][3][q0]     + BHr.x);
                float r1 = sigm(acc[mt][0][q0 + 1] + BIr.y + acc[mt][3][q0 + 1] + BHr.y);
                float z0 = sigm(acc[mt][1][q0]     + BIz.x + acc[mt][4][q0]     + BHz.x);
                float z1 = sigm(acc[mt][1][q0 + 1] + BIz.y + acc[mt][4][q0 + 1] + BHz.y);
                float n0 = tanhap(acc[mt][2][q0]     + BIn.x + r0 * (acc[mt][5][q0]     + BHn.x));
                float n1 = tanhap(acc[mt][2][q0 + 1] + BIn.y + r1 * (acc[mt][5][q0 + 1] + BHn.y));
                float hn0 = (1.0f - z0) * n0 + z0 * ho.x;
                float hn1 = (1.0f - z1) * n1 + z1 * ho.y;
                long long idx = (long long)(mrow0 + row) * H_ + e_colp;
                if (out32)
                    *(float2*)(out32 + idx) = make_float2(hn0, hn1);
                if (out16)
                    *(uint32_t*)(out16 + idx) = f16x2_of(hn0, hn1);
            }
        }

        // ---- close the tile: wait for next A, one barrier ----------------------
        if (it + 1 < NTILES) {
            CP_WAIT0();
            NB(rowg);
        }
        pb ^= 1;
    }
}

// ---------------------------------------------------------------------------
extern "C" void kernel_launch(void* const* d_in, const int* in_sizes, int n_in,
                              void* d_out, int out_size) {
    const float* seq_out     = (const float*)d_in[0];
    const int*   target_idxs = (const int*)  d_in[1];
    const int*   nid2rows    = (const int*)  d_in[2];
    const int*   ev_nids     = (const int*)  d_in[3];
    const float* adj         = (const float*)d_in[4];
    const float* adj_bias    = (const float*)d_in[5];
    const float* w_ih        = (const float*)d_in[6];
    const float* w_hh        = (const float*)d_in[7];
    const float* b_ih        = (const float*)d_in[8];
    const float* b_hh        = (const float*)d_in[9];
    float* out = (float*)d_out;

    static bool attr_set = false;
    if (!attr_set) {
        cudaFuncSetAttribute(gru_pass_kernel,
                             cudaFuncAttributeMaxDynamicSharedMemorySize,
                             SMEM_TOT);
        attr_set = true;
    }

    gather_adj_kernel<<<B_, 256>>>(seq_out, target_idxs, nid2rows, ev_nids,
                                   adj, adj_bias, w_ih, w_hh);

    __half *x16_p, *h16_p, *h216_p, *wih_p, *whh_p;
    cudaGetSymbolAddress((void**)&x16_p,  g_x16);
    cudaGetSymbolAddress((void**)&h16_p,  g_h16);
    cudaGetSymbolAddress((void**)&h216_p, g_h216);
    cudaGetSymbolAddress((void**)&wih_p,  g_wih16);
    cudaGetSymbolAddress((void**)&whh_p,  g_whh16);

    dim3 grid(MTOT / (64 * NTILES), 4);    // (32, 4) = 128 CTAs, 1 wave
    // pass 1: x = a, h = ev -> h1 (fp16 only)
    gru_pass_kernel<<<grid, 256, SMEM_TOT>>>(
        x16_p, h16_p, wih_p, whh_p, b_ih, b_hh,
        nullptr, h216_p);
    // pass 2: x = h = h1 (aliased -> A loads halved) -> d_out fp32
    gru_pass_kernel<<<grid, 256, SMEM_TOT>>>(
        h216_p, h216_p, wih_p, whh_p, b_ih, b_hh,
        out, nullptr);
}